// round 15
// baseline (speedup 1.0000x reference)
#include <cuda_runtime.h>
#include <cuda_bf16.h>
#include <cstdint>

typedef unsigned long long ull;

#define M_MODELS 3
#define B_IMG    16
#define N_BOX    512
#define K_TOT    (M_MODELS * N_BOX)   // 1536
#define PAD      2048
#define NUM_CLS  12
#define CPB      2                    // classes per NMS block
#define NMS_BLK  (B_IMG * NUM_CLS / CPB)    // 96
#define GRID     (B_IMG + NMS_BLK)          // 112 < 148 SMs -> single wave
#define CAPX     384                  // per-bucket extraction capacity
#define CAP      256                  // matrix fast-path capacity
#define W_MAX    4                    // CAP/64
#define THR      512

// ---------------- device scratch ----------------
__device__ float4        g_sbox[B_IMG * K_TOT];   // boxes by global rank
__device__ ull           g_skey[B_IMG * K_TOT];   // sort keys by global rank
__device__ unsigned char g_keep[B_IMG * K_TOT];   // keep flag by ORIGINAL element
__device__ int           g_done[B_IMG];           // arrival counters

__device__ __forceinline__ void cswap(ull& x, ull& y, bool up) {
    if ((x > y) == up) { ull t = x; x = y; y = t; }
}

__device__ __forceinline__ ull shfl_stage(ull v, int e, unsigned j, unsigned ks) {
    const ull  o     = __shfl_xor_sync(0xffffffffu, v, j);
    const bool up    = ((e & ks) == 0);
    const bool lower = ((e & j) == 0);
    return ((v < o) == (lower == up)) ? v : o;
}

// division-free exact IoU>0.5 test: 0.5*d is exact in fp32
__device__ __forceinline__ bool iou_gt(const float4 bi, const float ai,
                                       const float4 bj, const float aj) {
    const float iw = fmaxf(fminf(bi.z, bj.z) - fmaxf(bi.x, bj.x), 0.0f);
    const float ih = fmaxf(fminf(bi.w, bj.w) - fmaxf(bi.y, bj.y), 0.0f);
    const float inter = iw * ih;
    const float uni   = ai + aj - inter;
    return inter > 0.5f * fmaxf(uni, 1e-9f);
}

struct NmsSh {
    ull    skey[2][CAPX];          // 6144 B  (extraction order)
    ull    rkey[2][CAPX];          // 6144 B  (rank order)
    float4 bx[2][CAPX];            // 12288 B
    float  ar[2][CAPX];            // 3072 B
    ull    smask[2][CAP * W_MAX];  // 16384 B
    ull    rownz[2][W_MAX];
    ull    keepw[2][W_MAX];
};
union ShU {
    ull   key[PAD];                // sorter role (16 KB)
    NmsSh n;                       // nms role (~43.2 KB)
};

// =============================================================================
// ONE kernel, 112 blocks (single wave): 16 sorter blocks run CONCURRENTLY with
// 96 NMS blocks (2 classes each: shared extraction scan, rank-count sort,
// 8+8-warp matrix build, 2 parallel chases). Last of the 7 blocks per image
// joins rank data with keep flags and writes the output.
// =============================================================================
__global__ __launch_bounds__(THR)
void k_fused(const float* __restrict__ boxes, const float* __restrict__ scores,
             const int* __restrict__ labels, const float* __restrict__ weights,
             float* __restrict__ out) {
    __shared__ ShU sh;
    __shared__ int s_cnt2[2], s_last;

    const int bid  = blockIdx.x;
    const int tid  = threadIdx.x;
    const int warp = tid >> 5, lane = tid & 31;

    const float w0 = weights[0], w1 = weights[1], w2 = weights[2];

    int img;

    if (bid < B_IMG) {
        // =================== SORTER ROLE ===================
        img = bid;
        ull* key = sh.key;
        const int WB0 = warp << 7;   // 128-element window base

        auto mkkey = [&](int s) -> ull {
            if (s >= K_TOT) return ~0ull;
            const int m = s >> 9, n = s & (N_BOX - 1);
            const float wm = (m == 0) ? w0 : ((m == 1) ? w1 : w2);
            const float sc = scores[(m * B_IMG + img) * N_BOX + n] * wm;
            return ((ull)(~__float_as_uint(sc)) << 32) | (unsigned)s;
        };

        int e0 = WB0 + lane, e1 = e0 + 32, e2 = e0 + 64, e3 = e0 + 96;
        ull v0 = mkkey(e0), v1 = mkkey(e1), v2 = mkkey(e2), v3 = mkkey(e3);

        #pragma unroll
        for (int kb = 1; kb <= 5; kb++) {
            const unsigned ks = 1u << kb;
            const unsigned jstart = (ks > 32) ? 16u : (ks >> 1);
            #pragma unroll
            for (unsigned j = jstart; j >= 1; j >>= 1) {
                v0 = shfl_stage(v0, e0, j, ks);
                v1 = shfl_stage(v1, e1, j, ks);
                v2 = shfl_stage(v2, e2, j, ks);
                v3 = shfl_stage(v3, e3, j, ks);
            }
        }
        {   // ks = 64
            const unsigned ks = 64;
            cswap(v0, v1, ((e0 & ks) == 0));
            cswap(v2, v3, ((e2 & ks) == 0));
            #pragma unroll
            for (unsigned j = 16; j >= 1; j >>= 1) {
                v0 = shfl_stage(v0, e0, j, ks);
                v1 = shfl_stage(v1, e1, j, ks);
                v2 = shfl_stage(v2, e2, j, ks);
                v3 = shfl_stage(v3, e3, j, ks);
            }
        }
        {   // ks = 128
            const unsigned ks = 128;
            const bool up = ((e0 & ks) == 0);
            cswap(v0, v2, up); cswap(v1, v3, up);
            cswap(v0, v1, up); cswap(v2, v3, up);
            #pragma unroll
            for (unsigned j = 16; j >= 1; j >>= 1) {
                v0 = shfl_stage(v0, e0, j, ks);
                v1 = shfl_stage(v1, e1, j, ks);
                v2 = shfl_stage(v2, e2, j, ks);
                v3 = shfl_stage(v3, e3, j, ks);
            }
        }
        key[e0] = v0; key[e1] = v1; key[e2] = v2; key[e3] = v3;

        #pragma unroll
        for (unsigned ks = 256; ks <= PAD; ks <<= 1) {
            for (unsigned j = ks >> 1; j >= 128; j >>= 1) {
                __syncthreads();
                #pragma unroll
                for (int t = tid; t < 1024; t += THR) {
                    const unsigned i = (((unsigned)t & ~(j - 1)) << 1) | ((unsigned)t & (j - 1));
                    const unsigned p = i | j;
                    const ull x = key[i];
                    const ull y = key[p];
                    const bool up = ((i & ks) == 0);
                    if ((x > y) == up) { key[i] = y; key[p] = x; }
                }
            }
            __syncthreads();
            v0 = key[e0]; v1 = key[e1]; v2 = key[e2]; v3 = key[e3];
            const bool up = ((e0 & ks) == 0);
            cswap(v0, v2, up); cswap(v1, v3, up);
            cswap(v0, v1, up); cswap(v2, v3, up);
            #pragma unroll
            for (unsigned j = 16; j >= 1; j >>= 1) {
                v0 = shfl_stage(v0, e0, j, ks);
                v1 = shfl_stage(v1, e1, j, ks);
                v2 = shfl_stage(v2, e2, j, ks);
                v3 = shfl_stage(v3, e3, j, ks);
            }
            key[e0] = v0; key[e1] = v1; key[e2] = v2; key[e3] = v3;
        }
        __syncthreads();

        for (int r = tid; r < K_TOT; r += THR) {
            const ull kk = key[r];
            const int e = (int)(kk & 0xffffffffu);
            const int m = e >> 9, n = e & (N_BOX - 1);
            g_sbox[(size_t)img * K_TOT + r] =
                *(const float4*)&boxes[(((size_t)m * B_IMG + img) * N_BOX + n) * 4];
            g_skey[(size_t)img * K_TOT + r] = kk;
        }
    } else {
        // =================== NMS ROLE (2 classes) ===================
        const int idx = bid - B_IMG;
        img = idx / (NUM_CLS / CPB);
        const int cls0 = (idx % (NUM_CLS / CPB)) * CPB;

        if (tid < 2) s_cnt2[tid] = 0;
        if (tid >= 32 && tid < 32 + 2 * W_MAX) {
            const int t = tid - 32;
            sh.n.rownz[t / W_MAX][t % W_MAX] = 0ull;
            sh.n.keepw[t / W_MAX][t % W_MAX] = ~0ull;
        }
        __syncthreads();

        // ---- shared extraction scan for both classes ----
        for (int e = tid; e < K_TOT; e += THR) {
            const int m = e >> 9, n = e & (N_BOX - 1);
            const int lab = labels[(m * B_IMG + img) * N_BOX + n];
            const bool p0 = (lab == cls0);
            const bool p1 = (lab == cls0 + 1);
            ull kk = 0;
            if (p0 | p1) {
                const float wm = (m == 0) ? w0 : ((m == 1) ? w1 : w2);
                const float sc = scores[(m * B_IMG + img) * N_BOX + n] * wm;
                kk = ((ull)(~__float_as_uint(sc)) << 32) | (unsigned)e;
            }
            const unsigned bal0 = __ballot_sync(0xffffffffu, p0);
            const unsigned bal1 = __ballot_sync(0xffffffffu, p1);
            int b0 = 0, b1 = 0;
            if (lane == 0) {
                if (bal0) b0 = atomicAdd(&s_cnt2[0], __popc(bal0));
                if (bal1) b1 = atomicAdd(&s_cnt2[1], __popc(bal1));
            }
            b0 = __shfl_sync(0xffffffffu, b0, 0);
            b1 = __shfl_sync(0xffffffffu, b1, 0);
            if (p0) {
                const int pos = b0 + __popc(bal0 & ((1u << lane) - 1u));
                if (pos < CAPX) sh.n.skey[0][pos] = kk;
            }
            if (p1) {
                const int pos = b1 + __popc(bal1 & ((1u << lane) - 1u));
                if (pos < CAPX) sh.n.skey[1][pos] = kk;
            }
        }
        __syncthreads();
        const int cnt0 = min(s_cnt2[0], CAPX);
        const int cnt1 = min(s_cnt2[1], CAPX);

        // ---- rank-by-counting sort, both buckets (keys distinct) ----
        for (int x = tid; x < cnt0 + cnt1; x += THR) {
            const int side = (x >= cnt0);
            const int m    = side ? x - cnt0 : x;
            const int cc   = side ? cnt1 : cnt0;
            const ull k = sh.n.skey[side][m];
            int r = 0;
            for (int j = 0; j < cc; j++) r += (sh.n.skey[side][j] < k);
            sh.n.rkey[side][r] = k;
        }
        __syncthreads();

        // ---- gather boxes in rank order (+ sentinels for matrix path) ----
        const int Wd0 = (cnt0 + 63) >> 6, Wd1 = (cnt1 + 63) >> 6;
        const int cp0 = (cnt0 <= CAP) ? (Wd0 << 6) : cnt0;
        const int cp1 = (cnt1 <= CAP) ? (Wd1 << 6) : cnt1;
        for (int x = tid; x < cp0 + cp1; x += THR) {
            const int side = (x >= cp0);
            const int m    = side ? x - cp0 : x;
            const int cc   = side ? cnt1 : cnt0;
            if (m < cc) {
                const int e = (int)(sh.n.rkey[side][m] & 0xffffffffu);
                const int mm = e >> 9, nn = e & (N_BOX - 1);
                const float4 bb =
                    *(const float4*)&boxes[(((size_t)mm * B_IMG + img) * N_BOX + nn) * 4];
                sh.n.bx[side][m] = bb;
                sh.n.ar[side][m] = (bb.z - bb.x) * (bb.w - bb.y);
            } else {
                sh.n.bx[side][m] = make_float4(3e8f, 3e8f, 3e8f, 3e8f);  // never suppresses
                sh.n.ar[side][m] = 0.0f;
            }
        }
        __syncthreads();

        // ---- matrix build: warps 0-7 bucket0, 8-15 bucket1 ----
        {
            const int bkt = warp >> 3;
            const int wi  = warp & 7;
            const int cnt = bkt ? cnt1 : cnt0;
            const int W   = bkt ? Wd1 : Wd0;
            if (cnt > 0 && cnt <= CAP) {
                for (int r = wi; r < cnt; r += 8) {
                    const float4 bi = sh.n.bx[bkt][r];
                    const float  ai = sh.n.ar[bkt][r];
                    const int    wlo = r >> 6;
                    ull nz = 0ull;
                    for (int w = wlo; w < W; w++) {
                        const int j0 = (w << 6) + lane;
                        const bool q0 = iou_gt(bi, ai, sh.n.bx[bkt][j0],      sh.n.ar[bkt][j0]);
                        const bool q1 = iou_gt(bi, ai, sh.n.bx[bkt][j0 + 32], sh.n.ar[bkt][j0 + 32]);
                        ull mword = ((ull)__ballot_sync(0xffffffffu, q1) << 32)
                                  |        __ballot_sync(0xffffffffu, q0);
                        if (w == wlo)
                            mword &= ~((2ull << (r & 63)) - 1ull);   // clear j<=r
                        if (lane == 0) sh.n.smask[bkt][r * W_MAX + w] = mword;
                        nz |= mword;
                    }
                    if (lane == 0 && nz)
                        atomicOr(&sh.n.rownz[bkt][r >> 6], 1ull << (r & 63));
                }
            }
        }
        __syncthreads();

        // ---- two parallel chases (tid 0 / tid 256) ----
        if ((tid & 255) == 0) {
            const int bkt = tid >> 8;
            const int cnt = bkt ? cnt1 : cnt0;
            const int W   = bkt ? Wd1 : Wd0;
            if (cnt > 0 && cnt <= CAP) {
                ull rem0 = 0, rem1 = 0, rem2 = 0, rem3 = 0;
                #pragma unroll
                for (int w = 0; w < W_MAX; w++) {
                    if (w >= W) break;
                    ull act = sh.n.rownz[bkt][w];
                    ull rw  = (w == 0) ? rem0 : (w == 1) ? rem1 : (w == 2) ? rem2 : rem3;
                    act &= ~rw;
                    while (act) {
                        const int bit = __ffsll((long long)act) - 1;
                        act &= act - 1;
                        if (!((rw >> bit) & 1ull)) {
                            const int i = (w << 6) + bit;
                            const ull* row = &sh.n.smask[bkt][i * W_MAX];
                            if (w <= 0)          rem0 |= row[0];
                            if (w <= 1 && W > 1) rem1 |= row[1];
                            if (w <= 2 && W > 2) rem2 |= row[2];
                            if (w <= 3 && W > 3) rem3 |= row[3];
                            rw = (w == 0) ? rem0 : (w == 1) ? rem1 : (w == 2) ? rem2 : rem3;
                            act &= ~rw;
                        }
                    }
                }
                sh.n.keepw[bkt][0] = ~rem0; sh.n.keepw[bkt][1] = ~rem1;
                sh.n.keepw[bkt][2] = ~rem2; sh.n.keepw[bkt][3] = ~rem3;
            }
        }

        // ---- fallback (cnt > CAP, pathological): warp 4 = b0, warp 12 = b1 ----
        if ((warp == 4 && cnt0 > CAP) || (warp == 12 && cnt1 > CAP)) {
            const int bkt = warp >> 3;
            const int cnt = bkt ? cnt1 : cnt0;
            short* klist = (short*)sh.n.smask[bkt];
            int nk = 0;
            for (int c = 0; c < cnt; c++) {
                const float4 bc = sh.n.bx[bkt][c];
                const float  ac = sh.n.ar[bkt][c];
                bool sup = false;
                for (int k = lane; k < nk; k += 32) {
                    const int rr = klist[k];
                    if (iou_gt(bc, ac, sh.n.bx[bkt][rr], sh.n.ar[bkt][rr])) { sup = true; break; }
                }
                sup = (__ballot_sync(0xffffffffu, sup) != 0u);
                if (!sup) {
                    if (lane == 0) klist[nk] = (short)c;
                    nk++;
                }
                if (lane == 0) {
                    const int e = (int)(sh.n.rkey[bkt][c] & 0xffffffffu);
                    g_keep[(size_t)img * K_TOT + e] = (unsigned char)(sup ? 0 : 1);
                }
                __syncwarp();
            }
        }
        __syncthreads();

        // ---- write keep flags by ORIGINAL element index (fast path) ----
        for (int x = tid; x < cnt0 + cnt1; x += THR) {
            const int side = (x >= cnt0);
            const int m    = side ? x - cnt0 : x;
            const int cnt  = side ? cnt1 : cnt0;
            if (cnt <= CAP) {
                const int e = (int)(sh.n.rkey[side][m] & 0xffffffffu);
                g_keep[(size_t)img * K_TOT + e] =
                    (unsigned char)((sh.n.keepw[side][m >> 6] >> (m & 63)) & 1ull);
            }
        }
    }

    // ================= arrival + epilogue by last block of the image =========
    __threadfence();
    __syncthreads();
    if (tid == 0) {
        const int old = atomicAdd(&g_done[img], 1);
        s_last = (old == NUM_CLS / CPB);      // 7th arrival (0..6)
        if (s_last) __threadfence();
    }
    __syncthreads();

    if (s_last) {
        for (int r = tid; r < K_TOT; r += THR) {
            const ull kk = g_skey[(size_t)img * K_TOT + r];
            const int e = (int)(kk & 0xffffffffu);
            const float sc = __uint_as_float(~(unsigned)(kk >> 32));
            const float f = g_keep[(size_t)img * K_TOT + e] ? 1.0f : 0.0f;
            const float4 bb = g_sbox[(size_t)img * K_TOT + r];
            const size_t o = ((size_t)img * K_TOT + r) * 5;
            out[o + 0] = bb.x * f;
            out[o + 1] = bb.y * f;
            out[o + 2] = bb.z * f;
            out[o + 3] = bb.w * f;
            out[o + 4] = sc * f;
        }
        __syncthreads();
        if (tid == 0) g_done[img] = 0;   // reset for next graph replay
    }
}

// =============================================================================
extern "C" void kernel_launch(void* const* d_in, const int* in_sizes, int n_in,
                              void* d_out, int out_size) {
    const float* boxes   = (const float*)d_in[0];
    const float* scores  = (const float*)d_in[1];
    const int*   labels  = (const int*)  d_in[2];
    const float* weights = (const float*)d_in[3];
    float*       out     = (float*)d_out;

    k_fused<<<GRID, THR>>>(boxes, scores, labels, weights, out);
}